// round 12
// baseline (speedup 1.0000x reference)
#include <cuda_runtime.h>
#include <cuda_bf16.h>
#include <math.h>
#include <stdint.h>

// ---------------------------------------------------------------------------
// AttentionLayer B=16,T=1024,S=1024,C=1024,E=1024.
// Tensor-core GEMMs via mma.sync.m16n8k16 bf16. 3-term hi/lo split, fp32 acc.
// R12: 128x256 CTA tile, 512 threads, 1 CTA/SM, 3-stage cp.async —
// cuts LDGSTS-per-FLOP 25% (LSU-issue-bound model from R11 post-mortem).
// ---------------------------------------------------------------------------

#define BB 16
#define TTK 1024
#define SEQ 1024
#define NEL (16 * 1024 * 1024)

// ------------------------------ scratch -----------------------------------
__device__ float g_scores[NEL];
__device__ __align__(16) __nv_bfloat16 g_x_hi[NEL], g_x_lo[NEL];
__device__ __align__(16) __nv_bfloat16 g_h_hi[NEL], g_h_lo[NEL];
__device__ __align__(16) __nv_bfloat16 g_kT_hi[NEL], g_kT_lo[NEL];
__device__ __align__(16) __nv_bfloat16 g_vT_hi[NEL], g_vT_lo[NEL];
__device__ __align__(16) __nv_bfloat16 g_at_hi[NEL], g_at_lo[NEL];
__device__ __align__(16) __nv_bfloat16 g_cx_hi[NEL], g_cx_lo[NEL];
__device__ __align__(16) __nv_bfloat16 g_wi_hi[1024 * 1024], g_wi_lo[1024 * 1024];
__device__ __align__(16) __nv_bfloat16 g_wo_hi[1024 * 1024], g_wo_lo[1024 * 1024];
__device__ int g_cnt[BB];
__device__ unsigned char g_mask[BB * SEQ];

// ------------------------------ helpers ------------------------------------
static __device__ __forceinline__ uint32_t smem_u32(const void* p) {
    uint32_t a;
    asm("{ .reg .u64 t; cvta.to.shared.u64 t, %1; cvt.u32.u64 %0, t; }" : "=r"(a) : "l"(p));
    return a;
}
static __device__ __forceinline__ uint32_t pk2(float a, float b) {
    __nv_bfloat162 t = __floats2bfloat162_rn(a, b);
    return *(uint32_t*)&t;
}
static __device__ __forceinline__ float hif(float v) {
    return __bfloat162float(__float2bfloat16_rn(v));
}
static __device__ __forceinline__ void ldsm4(uint32_t* r, uint32_t addr) {
    asm volatile("ldmatrix.sync.aligned.m8n8.x4.shared.b16 {%0,%1,%2,%3}, [%4];"
                 : "=r"(r[0]), "=r"(r[1]), "=r"(r[2]), "=r"(r[3]) : "r"(addr));
}
static __device__ __forceinline__ void mma16816(float* d, const uint32_t* a,
                                                uint32_t b0, uint32_t b1) {
    asm volatile(
        "mma.sync.aligned.m16n8k16.row.col.f32.bf16.bf16.f32 "
        "{%0,%1,%2,%3}, {%4,%5,%6,%7}, {%8,%9}, {%0,%1,%2,%3};"
        : "+f"(d[0]), "+f"(d[1]), "+f"(d[2]), "+f"(d[3])
        : "r"(a[0]), "r"(a[1]), "r"(a[2]), "r"(a[3]), "r"(b0), "r"(b1));
}
#define CP_ASYNC16(dst, src) \
    asm volatile("cp.async.cg.shared.global [%0], [%1], 16;" :: "r"(dst), "l"(src))
#define CP_COMMIT() asm volatile("cp.async.commit_group;" ::: "memory")
#define CP_WAIT1() asm volatile("cp.async.wait_group 1;" ::: "memory")
#define CP_WAIT0() asm volatile("cp.async.wait_group 0;" ::: "memory")

// swizzle: 64B rows of 4x16B chunks; phys chunk = chunk ^ (row&3) ^ ((row>>2)&1)
static __device__ __forceinline__ uint32_t swz_off(int row, int chunk) {
    return (uint32_t)(row * 64 + ((chunk ^ (row & 3) ^ ((row >> 2) & 1)) << 4));
}

// --------------------- fused mask detect+expand+count ----------------------
__global__ void mask_fused_kernel(const void* __restrict__ mraw) {
    const unsigned int* mw = (const unsigned int*)mraw;
    __shared__ int sh_float, sh_big, sh_cnt[256];
    if (threadIdx.x == 0) { sh_float = 0; sh_big = 0; }
    __syncthreads();
    int ff = 0, fb = 0;
    for (int i = threadIdx.x; i < 4096; i += 256) {
        unsigned int w = mw[i];
        if (w == 0x3F800000u) ff = 1;
        else if (w > 1u) fb = 1;
    }
    if (ff) atomicOr(&sh_float, 1);
    if (fb) atomicOr(&sh_big, 1);
    __syncthreads();
    int mode = sh_float ? 2 : (sh_big ? 0 : 1);

    int i = blockIdx.x * 256 + threadIdx.x;   // 0..B*SEQ-1
    unsigned char v;
    if (mode == 1)      v = (((const int*)mraw)[i] != 0);
    else if (mode == 2) v = (((const float*)mraw)[i] != 0.0f);
    else                v = (((const unsigned char*)mraw)[i] != 0);
    g_mask[i] = v;

    sh_cnt[threadIdx.x] = v;
    __syncthreads();
    for (int o = 128; o > 0; o >>= 1) {
        if (threadIdx.x < o) sh_cnt[threadIdx.x] += sh_cnt[threadIdx.x + o];
        __syncthreads();
    }
    if (threadIdx.x == 0) atomicAdd(&g_cnt[i >> 10], sh_cnt[0]);
}

// ------------------------------ split kernels ------------------------------
__global__ void split_kernel(const float* __restrict__ src,
                             __nv_bfloat16* __restrict__ hi,
                             __nv_bfloat16* __restrict__ lo, long n4) {
    long i = (long)blockIdx.x * blockDim.x + threadIdx.x;
    if (i >= n4) return;
    float4 v = ((const float4*)src)[i];
    float hx = hif(v.x), hy = hif(v.y), hz = hif(v.z), hw = hif(v.w);
    ((uint2*)hi)[i] = make_uint2(pk2(v.x, v.y), pk2(v.z, v.w));
    ((uint2*)lo)[i] = make_uint2(pk2(v.x - hx, v.y - hy), pk2(v.z - hz, v.w - hw));
}

// transpose [bz][R][Cd] fp32 -> [bz][Cd][R] bf16 hi/lo
__global__ void transpose_split_kernel(const float* __restrict__ src,
                                       __nv_bfloat16* __restrict__ dhi,
                                       __nv_bfloat16* __restrict__ dlo,
                                       int R, int Cd) {
    __shared__ float tile[32][33];
    int bz = blockIdx.z;
    long base = (long)bz * R * Cd;
    int c0 = blockIdx.x * 32, r0 = blockIdx.y * 32;
    int tx = threadIdx.x, ty = threadIdx.y;
#pragma unroll
    for (int i = 0; i < 4; i++)
        tile[ty + i * 8][tx] = src[base + (long)(r0 + ty + i * 8) * Cd + c0 + tx];
    __syncthreads();
#pragma unroll
    for (int i = 0; i < 4; i++) {
        float v = tile[tx][ty + i * 8];
        long di = base + (long)(c0 + ty + i * 8) * R + r0 + tx;
        __nv_bfloat16 hb = __float2bfloat16_rn(v);
        dhi[di] = hb;
        dlo[di] = __float2bfloat16_rn(v - __bfloat162float(hb));
    }
}

// ------------------------------ mma.sync GEMM ------------------------------
// D[M,N] = A[M,K] @ B[N,K]^T, 3-term bf16 split, fp32 accum.
// CTA tile 128(M) x 256(N), 512 threads (16 warps: 2 M x 8 N), warp tile
// 64x32, K-chunk 32, 3-stage cp.async, 1 CTA/SM.
// EPI: 0 none, 1 (v+bias[n]+add[m,n])*scale, 2 v*sqrt(SEQ-cnt[bz])
// OUTM: 0 fp32 store, 1 split bf16 hi/lo store
#define STAGES 3
#define STAGE_BYTES 49152   // A hi/lo 128x32 (8KB each) + B hi/lo 256x32 (16KB each)
#define SMEMB (STAGES * STAGE_BYTES)

template <int EPI, int OUTM>
__global__ void __launch_bounds__(512, 1)
mma_gemm(const __nv_bfloat16* __restrict__ Ahi, const __nv_bfloat16* __restrict__ Alo,
         const __nv_bfloat16* __restrict__ Bhi, const __nv_bfloat16* __restrict__ Blo,
         float* __restrict__ Cf, __nv_bfloat16* __restrict__ Chi,
         __nv_bfloat16* __restrict__ Clo, int N, int K,
         long sA, long sB, long sC,
         const float* __restrict__ bias, const float* __restrict__ add, float scale,
         const int* __restrict__ cnt) {
    extern __shared__ char smem[];
    const int tid = threadIdx.x;
    const int wid = tid >> 5;
    const int lane = tid & 31;
    const int bx = blockIdx.x, by = blockIdx.y, bz = blockIdx.z;
    const uint32_t sb = smem_u32(smem);

    const __nv_bfloat16* srcA[4];
    srcA[0] = Ahi + bz * sA + (long)(by * 128) * K;   // A panel: 128 rows
    srcA[1] = Alo + bz * sA + (long)(by * 128) * K;
    srcA[2] = Bhi + bz * sB + (long)(bx * 256) * K;   // B panel: 256 rows
    srcA[3] = Blo + bz * sB + (long)(bx * 256) * K;

    const int NK = K >> 5;   // chunks of 32 K-elements

    auto load_stage = [&](int kc, int slot) {
        uint32_t st = sb + (uint32_t)slot * STAGE_BYTES;
        {   // A hi/lo: 128 rows x 4 chunks = 512 16B-chunks, 1 per thread each
            int row = tid >> 2;
            int chunk = tid & 3;
            uint32_t so = swz_off(row, chunk);
            long go = (long)row * K + kc * 32 + chunk * 8;
            CP_ASYNC16(st + so,         srcA[0] + go);
            CP_ASYNC16(st + 8192u + so, srcA[1] + go);
        }
#pragma unroll
        for (int i = 0; i < 2; i++) {  // B hi/lo: 256 rows x 4 chunks = 1024
            int idx = i * 512 + tid;
            int row = idx >> 2;
            int chunk = idx & 3;
            uint32_t so = swz_off(row, chunk);
            long go = (long)row * K + kc * 32 + chunk * 8;
            CP_ASYNC16(st + 16384u + so, srcA[2] + go);
            CP_ASYNC16(st + 32768u + so, srcA[3] + go);
        }
        CP_COMMIT();
    };

    // warp tiling: 2 warps along M (64 rows each), 8 along N (32 cols each)
    const int warp_m = (wid >> 3) * 64;
    const int warp_n = (wid & 7) * 32;

    float acc[4][4][4];
#pragma unroll
    for (int i = 0; i < 4; i++)
#pragma unroll
        for (int j = 0; j < 4; j++)
#pragma unroll
            for (int k = 0; k < 4; k++) acc[i][j][k] = 0.0f;

    // ldmatrix per-lane row/chunk components
    const int a_row_l = lane & 15;
    const int a_chunk_l = lane >> 4;
    const int b_row_l = ((lane >> 4) << 3) + (lane & 7);
    const int b_chunk_l = (lane >> 3) & 1;

    load_stage(0, 0);
    load_stage(1, 1);

    for (int kc = 0; kc < NK; kc++) {
        if (kc + 2 < NK) {
            CP_WAIT1();
        } else {
            CP_WAIT0();
        }
        // Single barrier: (a) slot-kc data visible, (b) all warps done with
        // slot kc-1 (the slot load_stage(kc+2) overwrites).
        __syncthreads();
        if (kc + 2 < NK) load_stage(kc + 2, (kc + 2) % STAGES);

        uint32_t st = sb + (uint32_t)(kc % STAGES) * STAGE_BYTES;
        uint32_t stA_hi = st, stA_lo = st + 8192u;
        uint32_t stB_hi = st + 16384u, stB_lo = st + 32768u;

#pragma unroll
        for (int ks = 0; ks < 2; ks++) {
            // A fragments (hi+lo) for all 4 m-tiles: 32 regs, reused across nt
            uint32_t afh[4][4], afl[4][4];
#pragma unroll
            for (int mt = 0; mt < 4; mt++) {
                int row = warp_m + mt * 16 + a_row_l;
                int chunk = ks * 2 + a_chunk_l;
                uint32_t off = swz_off(row, chunk);
                ldsm4(afh[mt], stA_hi + off);
                ldsm4(afl[mt], stA_lo + off);
            }
            // B fragments per ntp pair: short-lived (8 regs)
#pragma unroll
            for (int ntp = 0; ntp < 2; ntp++) {
                int row = warp_n + ntp * 16 + b_row_l;
                int chunk = ks * 2 + b_chunk_l;
                uint32_t off = swz_off(row, chunk);
                uint32_t rh[4], rl[4];
                ldsm4(rh, stB_hi + off);
                ldsm4(rl, stB_lo + off);
#pragma unroll
                for (int half = 0; half < 2; half++) {
                    int nt = ntp * 2 + half;
#pragma unroll
                    for (int mt = 0; mt < 4; mt++) {
                        mma16816(acc[mt][nt], afh[mt], rh[half * 2], rh[half * 2 + 1]);
                        mma16816(acc[mt][nt], afh[mt], rl[half * 2], rl[half * 2 + 1]);
                        mma16816(acc[mt][nt], afl[mt], rh[half * 2], rh[half * 2 + 1]);
                    }
                }
            }
        }
    }

    // ---------------- epilogue ----------------
    float rs = 1.0f;
    if (EPI == 2) rs = sqrtf((float)(SEQ - cnt[bz]));
    const long cbase = bz * sC;
    const int gid = lane >> 2;
    const int qid = (lane & 3) * 2;

#pragma unroll
    for (int mt = 0; mt < 4; mt++) {
#pragma unroll
        for (int nt = 0; nt < 4; nt++) {
            int m0 = by * 128 + warp_m + mt * 16 + gid;
            int n = bx * 256 + warp_n + nt * 8 + qid;
            const float* a4 = acc[mt][nt];
#pragma unroll
            for (int h = 0; h < 2; h++) {
                int m = m0 + h * 8;
                float v0 = a4[h * 2 + 0], v1 = a4[h * 2 + 1];
                if (EPI == 1) {
                    float2 ad = *(const float2*)(add + (long)m * N + n);
                    v0 = (v0 + __ldg(bias + n + 0) + ad.x) * scale;
                    v1 = (v1 + __ldg(bias + n + 1) + ad.y) * scale;
                } else if (EPI == 2) {
                    v0 *= rs; v1 *= rs;
                }
                long o = cbase + (long)m * N + n;
                if (OUTM == 0) {
                    float2 w; w.x = v0; w.y = v1;
                    *(float2*)(Cf + o) = w;
                } else {
                    float h0 = hif(v0), h1 = hif(v1);
                    *(uint32_t*)(Chi + o) = pk2(v0, v1);
                    *(uint32_t*)(Clo + o) = pk2(v0 - h0, v1 - h1);
                }
            }
        }
    }
}

// ------------------------------ softmax (+split) ---------------------------
__global__ void softmax_kernel(const float* __restrict__ scores,
                               float* __restrict__ attn,
                               __nv_bfloat16* __restrict__ ahi,
                               __nv_bfloat16* __restrict__ alo) {
    __shared__ float sh[8];
    long row = blockIdx.x;
    int b = (int)(row >> 10);
    const float* src = scores + row * (long)SEQ;
    long dbase = row * (long)SEQ;
    const unsigned char* mrow = g_mask + (long)b * SEQ;

    int t = threadIdx.x;
    float vals[4];
    float mx = -INFINITY;
#pragma unroll
    for (int i = 0; i < 4; i++) {
        int s = t + 256 * i;
        float v = mrow[s] ? -INFINITY : src[s];
        vals[i] = v;
        mx = fmaxf(mx, v);
    }
#pragma unroll
    for (int o = 16; o > 0; o >>= 1) mx = fmaxf(mx, __shfl_xor_sync(0xffffffffu, mx, o));
    if ((t & 31) == 0) sh[t >> 5] = mx;
    __syncthreads();
    mx = sh[0];
#pragma unroll
    for (int w = 1; w < 8; w++) mx = fmaxf(mx, sh[w]);
    __syncthreads();

    float sum = 0.0f;
#pragma unroll
    for (int i = 0; i < 4; i++) {
        float e = expf(vals[i] - mx);
        vals[i] = e;
        sum += e;
    }
#pragma unroll
    for (int o = 16; o > 0; o >>= 1) sum += __shfl_xor_sync(0xffffffffu, sum, o);
    if ((t & 31) == 0) sh[t >> 5] = sum;
    __syncthreads();
    sum = sh[0];
#pragma unroll
    for (int w = 1; w < 8; w++) sum += sh[w];

    float inv = 1.0f / sum;
#pragma unroll
    for (int i = 0; i < 4; i++) {
        int s = t + 256 * i;
        float e = vals[i] * inv;
        attn[dbase + s] = e;
        __nv_bfloat16 hb = __float2bfloat16_rn(e);
        ahi[dbase + s] = hb;
        alo[dbase + s] = __float2bfloat16_rn(e - __bfloat162float(hb));
    }
}

// ------------------------------ launch -------------------------------------
extern "C" void kernel_launch(void* const* d_in, const int* in_sizes, int n_in,
                              void* d_out, int out_size) {
    const float* x      = (const float*)d_in[0];
    const float* te     = (const float*)d_in[1];
    const float* keys   = (const float*)d_in[2];
    const float* values = (const float*)d_in[3];
    const void*  mask   = d_in[4];
    const float* w_in   = (const float*)d_in[5];
    const float* b_in   = (const float*)d_in[6];
    const float* w_out  = (const float*)d_in[7];
    const float* b_out  = (const float*)d_in[8];

    float* out  = (float*)d_out;
    float* attn = (float*)d_out + (size_t)NEL;

    float* scores; __nv_bfloat16 *xh, *xl, *hh, *hl, *kh, *kl, *vh, *vl;
    __nv_bfloat16 *ath, *atl, *ch, *cl, *wih, *wil, *woh, *wol;
    int* cnt = nullptr;
    cudaGetSymbolAddress((void**)&scores, g_scores);
    cudaGetSymbolAddress((void**)&xh, g_x_hi);   cudaGetSymbolAddress((void**)&xl, g_x_lo);
    cudaGetSymbolAddress((void**)&hh, g_h_hi);   cudaGetSymbolAddress((void**)&hl, g_h_lo);
    cudaGetSymbolAddress((void**)&kh, g_kT_hi);  cudaGetSymbolAddress((void**)&kl, g_kT_lo);
    cudaGetSymbolAddress((void**)&vh, g_vT_hi);  cudaGetSymbolAddress((void**)&vl, g_vT_lo);
    cudaGetSymbolAddress((void**)&ath, g_at_hi); cudaGetSymbolAddress((void**)&atl, g_at_lo);
    cudaGetSymbolAddress((void**)&ch, g_cx_hi);  cudaGetSymbolAddress((void**)&cl, g_cx_lo);
    cudaGetSymbolAddress((void**)&wih, g_wi_hi); cudaGetSymbolAddress((void**)&wil, g_wi_lo);
    cudaGetSymbolAddress((void**)&woh, g_wo_hi); cudaGetSymbolAddress((void**)&wol, g_wo_lo);
    cudaGetSymbolAddress((void**)&cnt, g_cnt);

    cudaFuncSetAttribute(mma_gemm<1, 1>, cudaFuncAttributeMaxDynamicSharedMemorySize, SMEMB);
    cudaFuncSetAttribute(mma_gemm<0, 0>, cudaFuncAttributeMaxDynamicSharedMemorySize, SMEMB);
    cudaFuncSetAttribute(mma_gemm<2, 1>, cudaFuncAttributeMaxDynamicSharedMemorySize, SMEMB);
    cudaFuncSetAttribute(mma_gemm<1, 0>, cudaFuncAttributeMaxDynamicSharedMemorySize, SMEMB);

    const float scale = 0.70710678118654752440f;
    const long batch = (long)TTK * 1024;

    // Side stream: mask work, keys/values transposes, w_out split — all
    // independent of the GEMM1 chain. Joined before GEMM2.
    cudaStream_t s2;
    cudaEvent_t eFork, eJoin;
    cudaStreamCreateWithFlags(&s2, cudaStreamNonBlocking);
    cudaEventCreateWithFlags(&eFork, cudaEventDisableTiming);
    cudaEventCreateWithFlags(&eJoin, cudaEventDisableTiming);

    cudaEventRecord(eFork, 0);
    cudaStreamWaitEvent(s2, eFork, 0);
    cudaMemsetAsync(cnt, 0, BB * sizeof(int), s2);
    mask_fused_kernel<<<BB * SEQ / 256, 256, 0, s2>>>(mask);
    transpose_split_kernel<<<dim3(32, 32, BB), dim3(32, 8), 0, s2>>>(
        keys, kh, kl, 1024, 1024);
    transpose_split_kernel<<<dim3(32, 32, BB), dim3(32, 8), 0, s2>>>(
        values, vh, vl, 1024, 1024);
    split_kernel<<<(1024 * 1024 / 4 + 255) / 256, 256, 0, s2>>>(
        w_out, woh, wol, 1024 * 1024 / 4);
    cudaEventRecord(eJoin, s2);

    // Main chain: starts immediately with GEMM1's dependencies.
    split_kernel<<<(NEL / 4 + 255) / 256, 256>>>(x, xh, xl, NEL / 4);
    split_kernel<<<(1024 * 1024 / 4 + 255) / 256, 256>>>(
        w_in, wih, wil, 1024 * 1024 / 4);

    // GEMM1: h = (x @ w_in^T + b_in + te) * scale  -> split h
    // M=16384 -> 128 row-tiles; N=1024 -> 4 col-tiles of 256
    mma_gemm<1, 1><<<dim3(4, 128, 1), 512, SMEMB>>>(
        xh, xl, wih, wil, nullptr, hh, hl, 1024, 1024, 0, 0, 0, b_in, te, scale,
        nullptr);

    // Join side stream (kT needed now; g_mask at softmax; vT/w_out/cnt later).
    cudaStreamWaitEvent(0, eJoin, 0);

    // GEMM2: scores = h @ keys (B = keys^T [S,E])
    mma_gemm<0, 0><<<dim3(4, 8, BB), 512, SMEMB>>>(
        hh, hl, kh, kl, scores, nullptr, nullptr, 1024, 1024,
        batch, batch, batch, nullptr, nullptr, 1.0f, nullptr);

    softmax_kernel<<<BB * TTK, 256>>>(scores, attn, ath, atl);

    // GEMM3: ctx = (attn @ values) * sqrt(SEQ-cnt)  (B = values^T) -> split ctx
    mma_gemm<2, 1><<<dim3(4, 8, BB), 512, SMEMB>>>(
        ath, atl, vh, vl, nullptr, ch, cl, 1024, 1024,
        batch, batch, batch, nullptr, nullptr, 1.0f, cnt);

    // GEMM4: out = (ctx @ w_out^T + b_out + x) * scale
    mma_gemm<1, 0><<<dim3(4, 128, 1), 512, SMEMB>>>(
        ch, cl, woh, wol, out, nullptr, nullptr, 1024, 1024,
        0, 0, 0, b_out, x, scale, nullptr);
}

// round 13
// speedup vs baseline: 1.1881x; 1.1881x over previous
#include <cuda_runtime.h>
#include <cuda_bf16.h>
#include <math.h>
#include <stdint.h>

// ---------------------------------------------------------------------------
// AttentionLayer B=16,T=1024,S=1024,C=1024,E=1024.
// Tensor-core GEMMs via mma.sync.m16n8k16 bf16. 3-term hi/lo split, fp32 acc.
// R13: R10 config (best known: 128x128 tile, 256 thr, 2 CTA/SM, 3-stage,
// single-sync mainloop, side-stream mask/transposes) + merged x/w_in split.
// ---------------------------------------------------------------------------

#define BB 16
#define TTK 1024
#define SEQ 1024
#define NEL (16 * 1024 * 1024)

// ------------------------------ scratch -----------------------------------
__device__ float g_scores[NEL];
__device__ __align__(16) __nv_bfloat16 g_x_hi[NEL], g_x_lo[NEL];
__device__ __align__(16) __nv_bfloat16 g_h_hi[NEL], g_h_lo[NEL];
__device__ __align__(16) __nv_bfloat16 g_kT_hi[NEL], g_kT_lo[NEL];
__device__ __align__(16) __nv_bfloat16 g_vT_hi[NEL], g_vT_lo[NEL];
__device__ __align__(16) __nv_bfloat16 g_at_hi[NEL], g_at_lo[NEL];
__device__ __align__(16) __nv_bfloat16 g_cx_hi[NEL], g_cx_lo[NEL];
__device__ __align__(16) __nv_bfloat16 g_wi_hi[1024 * 1024], g_wi_lo[1024 * 1024];
__device__ __align__(16) __nv_bfloat16 g_wo_hi[1024 * 1024], g_wo_lo[1024 * 1024];
__device__ int g_cnt[BB];
__device__ unsigned char g_mask[BB * SEQ];

// ------------------------------ helpers ------------------------------------
static __device__ __forceinline__ uint32_t smem_u32(const void* p) {
    uint32_t a;
    asm("{ .reg .u64 t; cvta.to.shared.u64 t, %1; cvt.u32.u64 %0, t; }" : "=r"(a) : "l"(p));
    return a;
}
static __device__ __forceinline__ uint32_t pk2(float a, float b) {
    __nv_bfloat162 t = __floats2bfloat162_rn(a, b);
    return *(uint32_t*)&t;
}
static __device__ __forceinline__ float hif(float v) {
    return __bfloat162float(__float2bfloat16_rn(v));
}
static __device__ __forceinline__ void ldsm4(uint32_t* r, uint32_t addr) {
    asm volatile("ldmatrix.sync.aligned.m8n8.x4.shared.b16 {%0,%1,%2,%3}, [%4];"
                 : "=r"(r[0]), "=r"(r[1]), "=r"(r[2]), "=r"(r[3]) : "r"(addr));
}
static __device__ __forceinline__ void mma16816(float* d, const uint32_t* a,
                                                uint32_t b0, uint32_t b1) {
    asm volatile(
        "mma.sync.aligned.m16n8k16.row.col.f32.bf16.bf16.f32 "
        "{%0,%1,%2,%3}, {%4,%5,%6,%7}, {%8,%9}, {%0,%1,%2,%3};"
        : "+f"(d[0]), "+f"(d[1]), "+f"(d[2]), "+f"(d[3])
        : "r"(a[0]), "r"(a[1]), "r"(a[2]), "r"(a[3]), "r"(b0), "r"(b1));
}
#define CP_ASYNC16(dst, src) \
    asm volatile("cp.async.cg.shared.global [%0], [%1], 16;" :: "r"(dst), "l"(src))
#define CP_COMMIT() asm volatile("cp.async.commit_group;" ::: "memory")
#define CP_WAIT1() asm volatile("cp.async.wait_group 1;" ::: "memory")
#define CP_WAIT0() asm volatile("cp.async.wait_group 0;" ::: "memory")

// swizzle: 64B rows of 4x16B chunks; phys chunk = chunk ^ (row&3) ^ ((row>>2)&1)
static __device__ __forceinline__ uint32_t swz_off(int row, int chunk) {
    return (uint32_t)(row * 64 + ((chunk ^ (row & 3) ^ ((row >> 2) & 1)) << 4));
}

// --------------------- fused mask detect+expand+count ----------------------
__global__ void mask_fused_kernel(const void* __restrict__ mraw) {
    const unsigned int* mw = (const unsigned int*)mraw;
    __shared__ int sh_float, sh_big, sh_cnt[256];
    if (threadIdx.x == 0) { sh_float = 0; sh_big = 0; }
    __syncthreads();
    int ff = 0, fb = 0;
    for (int i = threadIdx.x; i < 4096; i += 256) {
        unsigned int w = mw[i];
        if (w == 0x3F800000u) ff = 1;
        else if (w > 1u) fb = 1;
    }
    if (ff) atomicOr(&sh_float, 1);
    if (fb) atomicOr(&sh_big, 1);
    __syncthreads();
    int mode = sh_float ? 2 : (sh_big ? 0 : 1);

    int i = blockIdx.x * 256 + threadIdx.x;   // 0..B*SEQ-1
    unsigned char v;
    if (mode == 1)      v = (((const int*)mraw)[i] != 0);
    else if (mode == 2) v = (((const float*)mraw)[i] != 0.0f);
    else                v = (((const unsigned char*)mraw)[i] != 0);
    g_mask[i] = v;

    sh_cnt[threadIdx.x] = v;
    __syncthreads();
    for (int o = 128; o > 0; o >>= 1) {
        if (threadIdx.x < o) sh_cnt[threadIdx.x] += sh_cnt[threadIdx.x + o];
        __syncthreads();
    }
    if (threadIdx.x == 0) atomicAdd(&g_cnt[i >> 10], sh_cnt[0]);
}

// ------------------------------ split kernels ------------------------------
__global__ void split_kernel(const float* __restrict__ src,
                             __nv_bfloat16* __restrict__ hi,
                             __nv_bfloat16* __restrict__ lo, long n4) {
    long i = (long)blockIdx.x * blockDim.x + threadIdx.x;
    if (i >= n4) return;
    float4 v = ((const float4*)src)[i];
    float hx = hif(v.x), hy = hif(v.y), hz = hif(v.z), hw = hif(v.w);
    ((uint2*)hi)[i] = make_uint2(pk2(v.x, v.y), pk2(v.z, v.w));
    ((uint2*)lo)[i] = make_uint2(pk2(v.x - hx, v.y - hy), pk2(v.z - hz, v.w - hw));
}

// merged split: blocks [0, 16384) handle srcA (x, 16M elems); blocks
// [16384, 17408) handle srcB (w_in, 1M elems). One launch on the critical path.
__global__ void split2_kernel(const float* __restrict__ srcA,
                              __nv_bfloat16* __restrict__ hiA,
                              __nv_bfloat16* __restrict__ loA,
                              const float* __restrict__ srcB,
                              __nv_bfloat16* __restrict__ hiB,
                              __nv_bfloat16* __restrict__ loB) {
    long i;
    const float* src;
    __nv_bfloat16 *hi, *lo;
    if (blockIdx.x < 16384) {
        i = (long)blockIdx.x * 256 + threadIdx.x;           // 0 .. 4M-1 (x/4)
        src = srcA; hi = hiA; lo = loA;
    } else {
        i = (long)(blockIdx.x - 16384) * 256 + threadIdx.x; // 0 .. 256K-1 (w/4)
        src = srcB; hi = hiB; lo = loB;
    }
    float4 v = ((const float4*)src)[i];
    float hx = hif(v.x), hy = hif(v.y), hz = hif(v.z), hw = hif(v.w);
    ((uint2*)hi)[i] = make_uint2(pk2(v.x, v.y), pk2(v.z, v.w));
    ((uint2*)lo)[i] = make_uint2(pk2(v.x - hx, v.y - hy), pk2(v.z - hz, v.w - hw));
}

// transpose [bz][R][Cd] fp32 -> [bz][Cd][R] bf16 hi/lo
__global__ void transpose_split_kernel(const float* __restrict__ src,
                                       __nv_bfloat16* __restrict__ dhi,
                                       __nv_bfloat16* __restrict__ dlo,
                                       int R, int Cd) {
    __shared__ float tile[32][33];
    int bz = blockIdx.z;
    long base = (long)bz * R * Cd;
    int c0 = blockIdx.x * 32, r0 = blockIdx.y * 32;
    int tx = threadIdx.x, ty = threadIdx.y;
#pragma unroll
    for (int i = 0; i < 4; i++)
        tile[ty + i * 8][tx] = src[base + (long)(r0 + ty + i * 8) * Cd + c0 + tx];
    __syncthreads();
#pragma unroll
    for (int i = 0; i < 4; i++) {
        float v = tile[tx][ty + i * 8];
        long di = base + (long)(c0 + ty + i * 8) * R + r0 + tx;
        __nv_bfloat16 hb = __float2bfloat16_rn(v);
        dhi[di] = hb;
        dlo[di] = __float2bfloat16_rn(v - __bfloat162float(hb));
    }
}

// ------------------------------ mma.sync GEMM ------------------------------
// D[M,N] = A[M,K] @ B[N,K]^T, 3-term bf16 split, fp32 accum.
// CTA tile 128x128, warp tile 64x32, K-chunk 32, 3-stage cp.async, 2 CTA/SM.
// EPI: 0 none, 1 (v+bias[n]+add[m,n])*scale, 2 v*sqrt(SEQ-cnt[bz])
// OUTM: 0 fp32 store, 1 split bf16 hi/lo store
#define STAGES 3
#define STAGE_BYTES 32768          // 4 tiles x 128x32 bf16 (8KB each)
#define SMEMB (STAGES * STAGE_BYTES)

template <int EPI, int OUTM>
__global__ void __launch_bounds__(256, 2)
mma_gemm(const __nv_bfloat16* __restrict__ Ahi, const __nv_bfloat16* __restrict__ Alo,
         const __nv_bfloat16* __restrict__ Bhi, const __nv_bfloat16* __restrict__ Blo,
         float* __restrict__ Cf, __nv_bfloat16* __restrict__ Chi,
         __nv_bfloat16* __restrict__ Clo, int N, int K,
         long sA, long sB, long sC,
         const float* __restrict__ bias, const float* __restrict__ add, float scale,
         const int* __restrict__ cnt) {
    extern __shared__ char smem[];
    const int tid = threadIdx.x;
    const int wid = tid >> 5;
    const int lane = tid & 31;
    const int bx = blockIdx.x, by = blockIdx.y, bz = blockIdx.z;
    const uint32_t sb = smem_u32(smem);

    const __nv_bfloat16* srcA[4];
    srcA[0] = Ahi + bz * sA + (long)(by * 128) * K;
    srcA[1] = Alo + bz * sA + (long)(by * 128) * K;
    srcA[2] = Bhi + bz * sB + (long)(bx * 128) * K;
    srcA[3] = Blo + bz * sB + (long)(bx * 128) * K;

    const int NK = K >> 5;   // chunks of 32 K-elements

    auto load_stage = [&](int kc, int slot) {
        uint32_t st = sb + (uint32_t)slot * STAGE_BYTES;
#pragma unroll
        for (int t4 = 0; t4 < 4; t4++) {
#pragma unroll
            for (int i = 0; i < 2; i++) {
                int idx = i * 256 + tid;        // 0..511
                int row = idx >> 2;
                int chunk = idx & 3;
                uint32_t dst = st + (uint32_t)t4 * 8192u + swz_off(row, chunk);
                const __nv_bfloat16* src = srcA[t4] + (long)row * K + kc * 32 + chunk * 8;
                CP_ASYNC16(dst, src);
            }
        }
        CP_COMMIT();
    };

    // warp tiling: 2 warps along M (64 rows each), 4 along N (32 cols each)
    const int warp_m = (wid >> 2) * 64;
    const int warp_n = (wid & 3) * 32;

    float acc[4][4][4];
#pragma unroll
    for (int i = 0; i < 4; i++)
#pragma unroll
        for (int j = 0; j < 4; j++)
#pragma unroll
            for (int k = 0; k < 4; k++) acc[i][j][k] = 0.0f;

    // ldmatrix per-lane row/chunk components
    const int a_row_l = lane & 15;
    const int a_chunk_l = lane >> 4;
    const int b_row_l = ((lane >> 4) << 3) + (lane & 7);
    const int b_chunk_l = (lane >> 3) & 1;

    load_stage(0, 0);
    load_stage(1, 1);

    for (int kc = 0; kc < NK; kc++) {
        if (kc + 2 < NK) {
            CP_WAIT1();
        } else {
            CP_WAIT0();
        }
        // Single barrier: (a) slot-kc data visible, (b) all warps done with
        // slot kc-1 (the slot load_stage(kc+2) overwrites).
        __syncthreads();
        if (kc + 2 < NK) load_stage(kc + 2, (kc + 2) % STAGES);

        uint32_t st = sb + (uint32_t)(kc % STAGES) * STAGE_BYTES;
        uint32_t stA_hi = st, stA_lo = st + 8192u;
        uint32_t stB_hi = st + 16384u, stB_lo = st + 24576u;

#pragma unroll
        for (int ks = 0; ks < 2; ks++) {
            // A fragments (hi+lo) for all 4 m-tiles: 32 regs, reused across nt
            uint32_t afh[4][4], afl[4][4];
#pragma unroll
            for (int mt = 0; mt < 4; mt++) {
                int row = warp_m + mt * 16 + a_row_l;
                int chunk = ks * 2 + a_chunk_l;
                uint32_t off = swz_off(row, chunk);
                ldsm4(afh[mt], stA_hi + off);
                ldsm4(afl[mt], stA_lo + off);
            }
            // B fragments per ntp pair: short-lived (8 regs)
#pragma unroll
            for (int ntp = 0; ntp < 2; ntp++) {
                int row = warp_n + ntp * 16 + b_row_l;
                int chunk = ks * 2 + b_chunk_l;
                uint32_t off = swz_off(row, chunk);
                uint32_t rh[4], rl[4];
                ldsm4(rh, stB_hi + off);
                ldsm4(rl, stB_lo + off);
#pragma unroll
                for (int half = 0; half < 2; half++) {
                    int nt = ntp * 2 + half;
#pragma unroll
                    for (int mt = 0; mt < 4; mt++) {
                        mma16816(acc[mt][nt], afh[mt], rh[half * 2], rh[half * 2 + 1]);
                        mma16816(acc[mt][nt], afh[mt], rl[half * 2], rl[half * 2 + 1]);
                        mma16816(acc[mt][nt], afl[mt], rh[half * 2], rh[half * 2 + 1]);
                    }
                }
            }
        }
    }

    // ---------------- epilogue ----------------
    float rs = 1.0f;
    if (EPI == 2) rs = sqrtf((float)(SEQ - cnt[bz]));
    const long cbase = bz * sC;
    const int gid = lane >> 2;
    const int qid = (lane & 3) * 2;

#pragma unroll
    for (int mt = 0; mt < 4; mt++) {
#pragma unroll
        for (int nt = 0; nt < 4; nt++) {
            int m0 = by * 128 + warp_m + mt * 16 + gid;
            int n = bx * 128 + warp_n + nt * 8 + qid;
            const float* a4 = acc[mt][nt];
#pragma unroll
            for (int h = 0; h < 2; h++) {
                int m = m0 + h * 8;
                float v0 = a4[h * 2 + 0], v1 = a4[h * 2 + 1];
                if (EPI == 1) {
                    float2 ad = *(const float2*)(add + (long)m * N + n);
                    v0 = (v0 + __ldg(bias + n + 0) + ad.x) * scale;
                    v1 = (v1 + __ldg(bias + n + 1) + ad.y) * scale;
                } else if (EPI == 2) {
                    v0 *= rs; v1 *= rs;
                }
                long o = cbase + (long)m * N + n;
                if (OUTM == 0) {
                    float2 w; w.x = v0; w.y = v1;
                    *(float2*)(Cf + o) = w;
                } else {
                    float h0 = hif(v0), h1 = hif(v1);
                    *(uint32_t*)(Chi + o) = pk2(v0, v1);
                    *(uint32_t*)(Clo + o) = pk2(v0 - h0, v1 - h1);
                }
            }
        }
    }
}

// ------------------------------ softmax (+split) ---------------------------
__global__ void softmax_kernel(const float* __restrict__ scores,
                               float* __restrict__ attn,
                               __nv_bfloat16* __restrict__ ahi,
                               __nv_bfloat16* __restrict__ alo) {
    __shared__ float sh[8];
    long row = blockIdx.x;
    int b = (int)(row >> 10);
    const float* src = scores + row * (long)SEQ;
    long dbase = row * (long)SEQ;
    const unsigned char* mrow = g_mask + (long)b * SEQ;

    int t = threadIdx.x;
    float vals[4];
    float mx = -INFINITY;
#pragma unroll
    for (int i = 0; i < 4; i++) {
        int s = t + 256 * i;
        float v = mrow[s] ? -INFINITY : src[s];
        vals[i] = v;
        mx = fmaxf(mx, v);
    }
#pragma unroll
    for (int o = 16; o > 0; o >>= 1) mx = fmaxf(mx, __shfl_xor_sync(0xffffffffu, mx, o));
    if ((t & 31) == 0) sh[t >> 5] = mx;
    __syncthreads();
    mx = sh[0];
#pragma unroll
    for (int w = 1; w < 8; w++) mx = fmaxf(mx, sh[w]);
    __syncthreads();

    float sum = 0.0f;
#pragma unroll
    for (int i = 0; i < 4; i++) {
        float e = expf(vals[i] - mx);
        vals[i] = e;
        sum += e;
    }
#pragma unroll
    for (int o = 16; o > 0; o >>= 1) sum += __shfl_xor_sync(0xffffffffu, sum, o);
    if ((t & 31) == 0) sh[t >> 5] = sum;
    __syncthreads();
    sum = sh[0];
#pragma unroll
    for (int w = 1; w < 8; w++) sum += sh[w];

    float inv = 1.0f / sum;
#pragma unroll
    for (int i = 0; i < 4; i++) {
        int s = t + 256 * i;
        float e = vals[i] * inv;
        attn[dbase + s] = e;
        __nv_bfloat16 hb = __float2bfloat16_rn(e);
        ahi[dbase + s] = hb;
        alo[dbase + s] = __float2bfloat16_rn(e - __bfloat162float(hb));
    }
}

// ------------------------------ launch -------------------------------------
extern "C" void kernel_launch(void* const* d_in, const int* in_sizes, int n_in,
                              void* d_out, int out_size) {
    const float* x      = (const float*)d_in[0];
    const float* te     = (const float*)d_in[1];
    const float* keys   = (const float*)d_in[2];
    const float* values = (const float*)d_in[3];
    const void*  mask   = d_in[4];
    const float* w_in   = (const float*)d_in[5];
    const float* b_in   = (const float*)d_in[6];
    const float* w_out  = (const float*)d_in[7];
    const float* b_out  = (const float*)d_in[8];

    float* out  = (float*)d_out;
    float* attn = (float*)d_out + (size_t)NEL;

    float* scores; __nv_bfloat16 *xh, *xl, *hh, *hl, *kh, *kl, *vh, *vl;
    __nv_bfloat16 *ath, *atl, *ch, *cl, *wih, *wil, *woh, *wol;
    int* cnt = nullptr;
    cudaGetSymbolAddress((void**)&scores, g_scores);
    cudaGetSymbolAddress((void**)&xh, g_x_hi);   cudaGetSymbolAddress((void**)&xl, g_x_lo);
    cudaGetSymbolAddress((void**)&hh, g_h_hi);   cudaGetSymbolAddress((void**)&hl, g_h_lo);
    cudaGetSymbolAddress((void**)&kh, g_kT_hi);  cudaGetSymbolAddress((void**)&kl, g_kT_lo);
    cudaGetSymbolAddress((void**)&vh, g_vT_hi);  cudaGetSymbolAddress((void**)&vl, g_vT_lo);
    cudaGetSymbolAddress((void**)&ath, g_at_hi); cudaGetSymbolAddress((void**)&atl, g_at_lo);
    cudaGetSymbolAddress((void**)&ch, g_cx_hi);  cudaGetSymbolAddress((void**)&cl, g_cx_lo);
    cudaGetSymbolAddress((void**)&wih, g_wi_hi); cudaGetSymbolAddress((void**)&wil, g_wi_lo);
    cudaGetSymbolAddress((void**)&woh, g_wo_hi); cudaGetSymbolAddress((void**)&wol, g_wo_lo);
    cudaGetSymbolAddress((void**)&cnt, g_cnt);

    cudaFuncSetAttribute(mma_gemm<1, 1>, cudaFuncAttributeMaxDynamicSharedMemorySize, SMEMB);
    cudaFuncSetAttribute(mma_gemm<0, 0>, cudaFuncAttributeMaxDynamicSharedMemorySize, SMEMB);
    cudaFuncSetAttribute(mma_gemm<2, 1>, cudaFuncAttributeMaxDynamicSharedMemorySize, SMEMB);
    cudaFuncSetAttribute(mma_gemm<1, 0>, cudaFuncAttributeMaxDynamicSharedMemorySize, SMEMB);

    const float scale = 0.70710678118654752440f;
    const long batch = (long)TTK * 1024;

    // Side stream: mask work, keys/values transposes, w_out split — all
    // independent of the GEMM1 chain. Joined before GEMM2.
    cudaStream_t s2;
    cudaEvent_t eFork, eJoin;
    cudaStreamCreateWithFlags(&s2, cudaStreamNonBlocking);
    cudaEventCreateWithFlags(&eFork, cudaEventDisableTiming);
    cudaEventCreateWithFlags(&eJoin, cudaEventDisableTiming);

    cudaEventRecord(eFork, 0);
    cudaStreamWaitEvent(s2, eFork, 0);
    cudaMemsetAsync(cnt, 0, BB * sizeof(int), s2);
    mask_fused_kernel<<<BB * SEQ / 256, 256, 0, s2>>>(mask);
    transpose_split_kernel<<<dim3(32, 32, BB), dim3(32, 8), 0, s2>>>(
        keys, kh, kl, 1024, 1024);
    transpose_split_kernel<<<dim3(32, 32, BB), dim3(32, 8), 0, s2>>>(
        values, vh, vl, 1024, 1024);
    split_kernel<<<(1024 * 1024 / 4 + 255) / 256, 256, 0, s2>>>(
        w_out, woh, wol, 1024 * 1024 / 4);
    cudaEventRecord(eJoin, s2);

    // Main chain: merged x + w_in split, then GEMM1 immediately.
    split2_kernel<<<16384 + 1024, 256>>>(x, xh, xl, w_in, wih, wil);

    // GEMM1: h = (x @ w_in^T + b_in + te) * scale  -> split h
    mma_gemm<1, 1><<<dim3(8, 128, 1), 256, SMEMB>>>(
        xh, xl, wih, wil, nullptr, hh, hl, 1024, 1024, 0, 0, 0, b_in, te, scale,
        nullptr);

    // Join side stream (kT needed now; g_mask at softmax; vT/w_out/cnt later).
    cudaStreamWaitEvent(0, eJoin, 0);

    // GEMM2: scores = h @ keys (B = keys^T [S,E])
    mma_gemm<0, 0><<<dim3(8, 8, BB), 256, SMEMB>>>(
        hh, hl, kh, kl, scores, nullptr, nullptr, 1024, 1024,
        batch, batch, batch, nullptr, nullptr, 1.0f, nullptr);

    softmax_kernel<<<BB * TTK, 256>>>(scores, attn, ath, atl);

    // GEMM3: ctx = (attn @ values) * sqrt(SEQ-cnt)  (B = values^T) -> split ctx
    mma_gemm<2, 1><<<dim3(8, 8, BB), 256, SMEMB>>>(
        ath, atl, vh, vl, nullptr, ch, cl, 1024, 1024,
        batch, batch, batch, nullptr, nullptr, 1.0f, cnt);

    // GEMM4: out = (ctx @ w_out^T + b_out + x) * scale
    mma_gemm<1, 0><<<dim3(8, 128, 1), 256, SMEMB>>>(
        ch, cl, woh, wol, out, nullptr, nullptr, 1024, 1024,
        0, 0, 0, b_out, x, scale, nullptr);
}

// round 14
// speedup vs baseline: 1.2146x; 1.0223x over previous
#include <cuda_runtime.h>
#include <cuda_bf16.h>
#include <math.h>
#include <stdint.h>

// ---------------------------------------------------------------------------
// AttentionLayer B=16,T=1024,S=1024,C=1024,E=1024.
// Tensor-core GEMMs via mma.sync.m16n8k16 bf16. 3-term hi/lo split, fp32 acc.
// R14: R13 base + middle-section pipelining: GEMM2/softmax/GEMM3/GEMM4 split
// 6/10 across two streams so softmax hides under the other chain's GEMMs.
// ---------------------------------------------------------------------------

#define BB 16
#define TTK 1024
#define SEQ 1024
#define NEL (16 * 1024 * 1024)

// ------------------------------ scratch -----------------------------------
__device__ float g_scores[NEL];
__device__ __align__(16) __nv_bfloat16 g_x_hi[NEL], g_x_lo[NEL];
__device__ __align__(16) __nv_bfloat16 g_h_hi[NEL], g_h_lo[NEL];
__device__ __align__(16) __nv_bfloat16 g_kT_hi[NEL], g_kT_lo[NEL];
__device__ __align__(16) __nv_bfloat16 g_vT_hi[NEL], g_vT_lo[NEL];
__device__ __align__(16) __nv_bfloat16 g_at_hi[NEL], g_at_lo[NEL];
__device__ __align__(16) __nv_bfloat16 g_cx_hi[NEL], g_cx_lo[NEL];
__device__ __align__(16) __nv_bfloat16 g_wi_hi[1024 * 1024], g_wi_lo[1024 * 1024];
__device__ __align__(16) __nv_bfloat16 g_wo_hi[1024 * 1024], g_wo_lo[1024 * 1024];
__device__ int g_cnt[BB];
__device__ unsigned char g_mask[BB * SEQ];

// ------------------------------ helpers ------------------------------------
static __device__ __forceinline__ uint32_t smem_u32(const void* p) {
    uint32_t a;
    asm("{ .reg .u64 t; cvta.to.shared.u64 t, %1; cvt.u32.u64 %0, t; }" : "=r"(a) : "l"(p));
    return a;
}
static __device__ __forceinline__ uint32_t pk2(float a, float b) {
    __nv_bfloat162 t = __floats2bfloat162_rn(a, b);
    return *(uint32_t*)&t;
}
static __device__ __forceinline__ float hif(float v) {
    return __bfloat162float(__float2bfloat16_rn(v));
}
static __device__ __forceinline__ void ldsm4(uint32_t* r, uint32_t addr) {
    asm volatile("ldmatrix.sync.aligned.m8n8.x4.shared.b16 {%0,%1,%2,%3}, [%4];"
                 : "=r"(r[0]), "=r"(r[1]), "=r"(r[2]), "=r"(r[3]) : "r"(addr));
}
static __device__ __forceinline__ void mma16816(float* d, const uint32_t* a,
                                                uint32_t b0, uint32_t b1) {
    asm volatile(
        "mma.sync.aligned.m16n8k16.row.col.f32.bf16.bf16.f32 "
        "{%0,%1,%2,%3}, {%4,%5,%6,%7}, {%8,%9}, {%0,%1,%2,%3};"
        : "+f"(d[0]), "+f"(d[1]), "+f"(d[2]), "+f"(d[3])
        : "r"(a[0]), "r"(a[1]), "r"(a[2]), "r"(a[3]), "r"(b0), "r"(b1));
}
#define CP_ASYNC16(dst, src) \
    asm volatile("cp.async.cg.shared.global [%0], [%1], 16;" :: "r"(dst), "l"(src))
#define CP_COMMIT() asm volatile("cp.async.commit_group;" ::: "memory")
#define CP_WAIT1() asm volatile("cp.async.wait_group 1;" ::: "memory")
#define CP_WAIT0() asm volatile("cp.async.wait_group 0;" ::: "memory")

// swizzle: 64B rows of 4x16B chunks; phys chunk = chunk ^ (row&3) ^ ((row>>2)&1)
static __device__ __forceinline__ uint32_t swz_off(int row, int chunk) {
    return (uint32_t)(row * 64 + ((chunk ^ (row & 3) ^ ((row >> 2) & 1)) << 4));
}

// --------------------- fused mask detect+expand+count ----------------------
__global__ void mask_fused_kernel(const void* __restrict__ mraw) {
    const unsigned int* mw = (const unsigned int*)mraw;
    __shared__ int sh_float, sh_big, sh_cnt[256];
    if (threadIdx.x == 0) { sh_float = 0; sh_big = 0; }
    __syncthreads();
    int ff = 0, fb = 0;
    for (int i = threadIdx.x; i < 4096; i += 256) {
        unsigned int w = mw[i];
        if (w == 0x3F800000u) ff = 1;
        else if (w > 1u) fb = 1;
    }
    if (ff) atomicOr(&sh_float, 1);
    if (fb) atomicOr(&sh_big, 1);
    __syncthreads();
    int mode = sh_float ? 2 : (sh_big ? 0 : 1);

    int i = blockIdx.x * 256 + threadIdx.x;   // 0..B*SEQ-1
    unsigned char v;
    if (mode == 1)      v = (((const int*)mraw)[i] != 0);
    else if (mode == 2) v = (((const float*)mraw)[i] != 0.0f);
    else                v = (((const unsigned char*)mraw)[i] != 0);
    g_mask[i] = v;

    sh_cnt[threadIdx.x] = v;
    __syncthreads();
    for (int o = 128; o > 0; o >>= 1) {
        if (threadIdx.x < o) sh_cnt[threadIdx.x] += sh_cnt[threadIdx.x + o];
        __syncthreads();
    }
    if (threadIdx.x == 0) atomicAdd(&g_cnt[i >> 10], sh_cnt[0]);
}

// ------------------------------ split kernels ------------------------------
__global__ void split_kernel(const float* __restrict__ src,
                             __nv_bfloat16* __restrict__ hi,
                             __nv_bfloat16* __restrict__ lo, long n4) {
    long i = (long)blockIdx.x * blockDim.x + threadIdx.x;
    if (i >= n4) return;
    float4 v = ((const float4*)src)[i];
    float hx = hif(v.x), hy = hif(v.y), hz = hif(v.z), hw = hif(v.w);
    ((uint2*)hi)[i] = make_uint2(pk2(v.x, v.y), pk2(v.z, v.w));
    ((uint2*)lo)[i] = make_uint2(pk2(v.x - hx, v.y - hy), pk2(v.z - hz, v.w - hw));
}

// merged split: blocks [0, 16384) handle srcA (x); rest handle srcB (w_in).
__global__ void split2_kernel(const float* __restrict__ srcA,
                              __nv_bfloat16* __restrict__ hiA,
                              __nv_bfloat16* __restrict__ loA,
                              const float* __restrict__ srcB,
                              __nv_bfloat16* __restrict__ hiB,
                              __nv_bfloat16* __restrict__ loB) {
    long i;
    const float* src;
    __nv_bfloat16 *hi, *lo;
    if (blockIdx.x < 16384) {
        i = (long)blockIdx.x * 256 + threadIdx.x;
        src = srcA; hi = hiA; lo = loA;
    } else {
        i = (long)(blockIdx.x - 16384) * 256 + threadIdx.x;
        src = srcB; hi = hiB; lo = loB;
    }
    float4 v = ((const float4*)src)[i];
    float hx = hif(v.x), hy = hif(v.y), hz = hif(v.z), hw = hif(v.w);
    ((uint2*)hi)[i] = make_uint2(pk2(v.x, v.y), pk2(v.z, v.w));
    ((uint2*)lo)[i] = make_uint2(pk2(v.x - hx, v.y - hy), pk2(v.z - hz, v.w - hw));
}

// transpose [bz][R][Cd] fp32 -> [bz][Cd][R] bf16 hi/lo
__global__ void transpose_split_kernel(const float* __restrict__ src,
                                       __nv_bfloat16* __restrict__ dhi,
                                       __nv_bfloat16* __restrict__ dlo,
                                       int R, int Cd) {
    __shared__ float tile[32][33];
    int bz = blockIdx.z;
    long base = (long)bz * R * Cd;
    int c0 = blockIdx.x * 32, r0 = blockIdx.y * 32;
    int tx = threadIdx.x, ty = threadIdx.y;
#pragma unroll
    for (int i = 0; i < 4; i++)
        tile[ty + i * 8][tx] = src[base + (long)(r0 + ty + i * 8) * Cd + c0 + tx];
    __syncthreads();
#pragma unroll
    for (int i = 0; i < 4; i++) {
        float v = tile[tx][ty + i * 8];
        long di = base + (long)(c0 + ty + i * 8) * R + r0 + tx;
        __nv_bfloat16 hb = __float2bfloat16_rn(v);
        dhi[di] = hb;
        dlo[di] = __float2bfloat16_rn(v - __bfloat162float(hb));
    }
}

// ------------------------------ mma.sync GEMM ------------------------------
// D[M,N] = A[M,K] @ B[N,K]^T, 3-term bf16 split, fp32 accum.
// CTA tile 128x128, warp tile 64x32, K-chunk 32, 3-stage cp.async, 2 CTA/SM.
// EPI: 0 none, 1 (v+bias[n]+add[m,n])*scale, 2 v*sqrt(SEQ-cnt[bz])
// OUTM: 0 fp32 store, 1 split bf16 hi/lo store
#define STAGES 3
#define STAGE_BYTES 32768          // 4 tiles x 128x32 bf16 (8KB each)
#define SMEMB (STAGES * STAGE_BYTES)

template <int EPI, int OUTM>
__global__ void __launch_bounds__(256, 2)
mma_gemm(const __nv_bfloat16* __restrict__ Ahi, const __nv_bfloat16* __restrict__ Alo,
         const __nv_bfloat16* __restrict__ Bhi, const __nv_bfloat16* __restrict__ Blo,
         float* __restrict__ Cf, __nv_bfloat16* __restrict__ Chi,
         __nv_bfloat16* __restrict__ Clo, int N, int K,
         long sA, long sB, long sC,
         const float* __restrict__ bias, const float* __restrict__ add, float scale,
         const int* __restrict__ cnt) {
    extern __shared__ char smem[];
    const int tid = threadIdx.x;
    const int wid = tid >> 5;
    const int lane = tid & 31;
    const int bx = blockIdx.x, by = blockIdx.y, bz = blockIdx.z;
    const uint32_t sb = smem_u32(smem);

    const __nv_bfloat16* srcA[4];
    srcA[0] = Ahi + bz * sA + (long)(by * 128) * K;
    srcA[1] = Alo + bz * sA + (long)(by * 128) * K;
    srcA[2] = Bhi + bz * sB + (long)(bx * 128) * K;
    srcA[3] = Blo + bz * sB + (long)(bx * 128) * K;

    const int NK = K >> 5;   // chunks of 32 K-elements

    auto load_stage = [&](int kc, int slot) {
        uint32_t st = sb + (uint32_t)slot * STAGE_BYTES;
#pragma unroll
        for (int t4 = 0; t4 < 4; t4++) {
#pragma unroll
            for (int i = 0; i < 2; i++) {
                int idx = i * 256 + tid;        // 0..511
                int row = idx >> 2;
                int chunk = idx & 3;
                uint32_t dst = st + (uint32_t)t4 * 8192u + swz_off(row, chunk);
                const __nv_bfloat16* src = srcA[t4] + (long)row * K + kc * 32 + chunk * 8;
                CP_ASYNC16(dst, src);
            }
        }
        CP_COMMIT();
    };

    // warp tiling: 2 warps along M (64 rows each), 4 along N (32 cols each)
    const int warp_m = (wid >> 2) * 64;
    const int warp_n = (wid & 3) * 32;

    float acc[4][4][4];
#pragma unroll
    for (int i = 0; i < 4; i++)
#pragma unroll
        for (int j = 0; j < 4; j++)
#pragma unroll
            for (int k = 0; k < 4; k++) acc[i][j][k] = 0.0f;

    // ldmatrix per-lane row/chunk components
    const int a_row_l = lane & 15;
    const int a_chunk_l = lane >> 4;
    const int b_row_l = ((lane >> 4) << 3) + (lane & 7);
    const int b_chunk_l = (lane >> 3) & 1;

    load_stage(0, 0);
    load_stage(1, 1);

    for (int kc = 0; kc < NK; kc++) {
        if (kc + 2 < NK) {
            CP_WAIT1();
        } else {
            CP_WAIT0();
        }
        // Single barrier: (a) slot-kc data visible, (b) all warps done with
        // slot kc-1 (the slot load_stage(kc+2) overwrites).
        __syncthreads();
        if (kc + 2 < NK) load_stage(kc + 2, (kc + 2) % STAGES);

        uint32_t st = sb + (uint32_t)(kc % STAGES) * STAGE_BYTES;
        uint32_t stA_hi = st, stA_lo = st + 8192u;
        uint32_t stB_hi = st + 16384u, stB_lo = st + 24576u;

#pragma unroll
        for (int ks = 0; ks < 2; ks++) {
            // A fragments (hi+lo) for all 4 m-tiles: 32 regs, reused across nt
            uint32_t afh[4][4], afl[4][4];
#pragma unroll
            for (int mt = 0; mt < 4; mt++) {
                int row = warp_m + mt * 16 + a_row_l;
                int chunk = ks * 2 + a_chunk_l;
                uint32_t off = swz_off(row, chunk);
                ldsm4(afh[mt], stA_hi + off);
                ldsm4(afl[mt], stA_lo + off);
            }
            // B fragments per ntp pair: short-lived (8 regs)
#pragma unroll
            for (int ntp = 0; ntp < 2; ntp++) {
                int row = warp_n + ntp * 16 + b_row_l;
                int chunk = ks * 2 + b_chunk_l;
                uint32_t off = swz_off(row, chunk);
                uint32_t rh[4], rl[4];
                ldsm4(rh, stB_hi + off);
                ldsm4(rl, stB_lo + off);
#pragma unroll
                for (int half = 0; half < 2; half++) {
                    int nt = ntp * 2 + half;
#pragma unroll
                    for (int mt = 0; mt < 4; mt++) {
                        mma16816(acc[mt][nt], afh[mt], rh[half * 2], rh[half * 2 + 1]);
                        mma16816(acc[mt][nt], afh[mt], rl[half * 2], rl[half * 2 + 1]);
                        mma16816(acc[mt][nt], afl[mt], rh[half * 2], rh[half * 2 + 1]);
                    }
                }
            }
        }
    }

    // ---------------- epilogue ----------------
    float rs = 1.0f;
    if (EPI == 2) rs = sqrtf((float)(SEQ - cnt[bz]));
    const long cbase = bz * sC;
    const int gid = lane >> 2;
    const int qid = (lane & 3) * 2;

#pragma unroll
    for (int mt = 0; mt < 4; mt++) {
#pragma unroll
        for (int nt = 0; nt < 4; nt++) {
            int m0 = by * 128 + warp_m + mt * 16 + gid;
            int n = bx * 128 + warp_n + nt * 8 + qid;
            const float* a4 = acc[mt][nt];
#pragma unroll
            for (int h = 0; h < 2; h++) {
                int m = m0 + h * 8;
                float v0 = a4[h * 2 + 0], v1 = a4[h * 2 + 1];
                if (EPI == 1) {
                    float2 ad = *(const float2*)(add + (long)m * N + n);
                    v0 = (v0 + __ldg(bias + n + 0) + ad.x) * scale;
                    v1 = (v1 + __ldg(bias + n + 1) + ad.y) * scale;
                } else if (EPI == 2) {
                    v0 *= rs; v1 *= rs;
                }
                long o = cbase + (long)m * N + n;
                if (OUTM == 0) {
                    float2 w; w.x = v0; w.y = v1;
                    *(float2*)(Cf + o) = w;
                } else {
                    float h0 = hif(v0), h1 = hif(v1);
                    *(uint32_t*)(Chi + o) = pk2(v0, v1);
                    *(uint32_t*)(Clo + o) = pk2(v0 - h0, v1 - h1);
                }
            }
        }
    }
}

// ------------------------------ softmax (+split) ---------------------------
__global__ void softmax_kernel(const float* __restrict__ scores,
                               float* __restrict__ attn,
                               __nv_bfloat16* __restrict__ ahi,
                               __nv_bfloat16* __restrict__ alo,
                               const unsigned char* __restrict__ maskbase) {
    __shared__ float sh[8];
    long row = blockIdx.x;
    int b = (int)(row >> 10);
    const float* src = scores + row * (long)SEQ;
    long dbase = row * (long)SEQ;
    const unsigned char* mrow = maskbase + (long)b * SEQ;

    int t = threadIdx.x;
    float vals[4];
    float mx = -INFINITY;
#pragma unroll
    for (int i = 0; i < 4; i++) {
        int s = t + 256 * i;
        float v = mrow[s] ? -INFINITY : src[s];
        vals[i] = v;
        mx = fmaxf(mx, v);
    }
#pragma unroll
    for (int o = 16; o > 0; o >>= 1) mx = fmaxf(mx, __shfl_xor_sync(0xffffffffu, mx, o));
    if ((t & 31) == 0) sh[t >> 5] = mx;
    __syncthreads();
    mx = sh[0];
#pragma unroll
    for (int w = 1; w < 8; w++) mx = fmaxf(mx, sh[w]);
    __syncthreads();

    float sum = 0.0f;
#pragma unroll
    for (int i = 0; i < 4; i++) {
        float e = expf(vals[i] - mx);
        vals[i] = e;
        sum += e;
    }
#pragma unroll
    for (int o = 16; o > 0; o >>= 1) sum += __shfl_xor_sync(0xffffffffu, sum, o);
    if ((t & 31) == 0) sh[t >> 5] = sum;
    __syncthreads();
    sum = sh[0];
#pragma unroll
    for (int w = 1; w < 8; w++) sum += sh[w];

    float inv = 1.0f / sum;
#pragma unroll
    for (int i = 0; i < 4; i++) {
        int s = t + 256 * i;
        float e = vals[i] * inv;
        attn[dbase + s] = e;
        __nv_bfloat16 hb = __float2bfloat16_rn(e);
        ahi[dbase + s] = hb;
        alo[dbase + s] = __float2bfloat16_rn(e - __bfloat162float(hb));
    }
}

// ------------------------------ launch -------------------------------------
extern "C" void kernel_launch(void* const* d_in, const int* in_sizes, int n_in,
                              void* d_out, int out_size) {
    const float* x      = (const float*)d_in[0];
    const float* te     = (const float*)d_in[1];
    const float* keys   = (const float*)d_in[2];
    const float* values = (const float*)d_in[3];
    const void*  mask   = d_in[4];
    const float* w_in   = (const float*)d_in[5];
    const float* b_in   = (const float*)d_in[6];
    const float* w_out  = (const float*)d_in[7];
    const float* b_out  = (const float*)d_in[8];

    float* out  = (float*)d_out;
    float* attn = (float*)d_out + (size_t)NEL;

    float* scores; __nv_bfloat16 *xh, *xl, *hh, *hl, *kh, *kl, *vh, *vl;
    __nv_bfloat16 *ath, *atl, *ch, *cl, *wih, *wil, *woh, *wol;
    int* cnt = nullptr; unsigned char* mk = nullptr;
    cudaGetSymbolAddress((void**)&scores, g_scores);
    cudaGetSymbolAddress((void**)&xh, g_x_hi);   cudaGetSymbolAddress((void**)&xl, g_x_lo);
    cudaGetSymbolAddress((void**)&hh, g_h_hi);   cudaGetSymbolAddress((void**)&hl, g_h_lo);
    cudaGetSymbolAddress((void**)&kh, g_kT_hi);  cudaGetSymbolAddress((void**)&kl, g_kT_lo);
    cudaGetSymbolAddress((void**)&vh, g_vT_hi);  cudaGetSymbolAddress((void**)&vl, g_vT_lo);
    cudaGetSymbolAddress((void**)&ath, g_at_hi); cudaGetSymbolAddress((void**)&atl, g_at_lo);
    cudaGetSymbolAddress((void**)&ch, g_cx_hi);  cudaGetSymbolAddress((void**)&cl, g_cx_lo);
    cudaGetSymbolAddress((void**)&wih, g_wi_hi); cudaGetSymbolAddress((void**)&wil, g_wi_lo);
    cudaGetSymbolAddress((void**)&woh, g_wo_hi); cudaGetSymbolAddress((void**)&wol, g_wo_lo);
    cudaGetSymbolAddress((void**)&cnt, g_cnt);
    cudaGetSymbolAddress((void**)&mk, g_mask);

    cudaFuncSetAttribute(mma_gemm<1, 1>, cudaFuncAttributeMaxDynamicSharedMemorySize, SMEMB);
    cudaFuncSetAttribute(mma_gemm<0, 0>, cudaFuncAttributeMaxDynamicSharedMemorySize, SMEMB);
    cudaFuncSetAttribute(mma_gemm<2, 1>, cudaFuncAttributeMaxDynamicSharedMemorySize, SMEMB);
    cudaFuncSetAttribute(mma_gemm<1, 0>, cudaFuncAttributeMaxDynamicSharedMemorySize, SMEMB);

    const float scale = 0.70710678118654752440f;
    const long batch = (long)TTK * 1024;

    // Batch split for the middle pipeline: A = batches [0,6), B = [6,16).
    const int NBA = 6, NBB = 10;
    const long offB = (long)NBA * batch;      // element offset of chain B

    cudaStream_t s2;
    cudaEvent_t eFork, eJoin, eG1, eB;
    cudaStreamCreateWithFlags(&s2, cudaStreamNonBlocking);
    cudaEventCreateWithFlags(&eFork, cudaEventDisableTiming);
    cudaEventCreateWithFlags(&eJoin, cudaEventDisableTiming);
    cudaEventCreateWithFlags(&eG1, cudaEventDisableTiming);
    cudaEventCreateWithFlags(&eB, cudaEventDisableTiming);

    cudaEventRecord(eFork, 0);
    cudaStreamWaitEvent(s2, eFork, 0);
    cudaMemsetAsync(cnt, 0, BB * sizeof(int), s2);
    mask_fused_kernel<<<BB * SEQ / 256, 256, 0, s2>>>(mask);
    transpose_split_kernel<<<dim3(32, 32, BB), dim3(32, 8), 0, s2>>>(
        keys, kh, kl, 1024, 1024);
    transpose_split_kernel<<<dim3(32, 32, BB), dim3(32, 8), 0, s2>>>(
        values, vh, vl, 1024, 1024);
    split_kernel<<<(1024 * 1024 / 4 + 255) / 256, 256, 0, s2>>>(
        w_out, woh, wol, 1024 * 1024 / 4);
    cudaEventRecord(eJoin, s2);

    // Main chain: merged x + w_in split, then GEMM1 (full width).
    split2_kernel<<<16384 + 1024, 256>>>(x, xh, xl, w_in, wih, wil);
    mma_gemm<1, 1><<<dim3(8, 128, 1), 256, SMEMB>>>(
        xh, xl, wih, wil, nullptr, hh, hl, 1024, 1024, 0, 0, 0, b_in, te, scale,
        nullptr);
    cudaEventRecord(eG1, 0);

    // ---- Chain A (main): batches [0,6) ----
    cudaStreamWaitEvent(0, eJoin, 0);   // kT/mask/vT/w_out/cnt ready
    mma_gemm<0, 0><<<dim3(8, 8, NBA), 256, SMEMB>>>(
        hh, hl, kh, kl, scores, nullptr, nullptr, 1024, 1024,
        batch, batch, batch, nullptr, nullptr, 1.0f, nullptr);
    softmax_kernel<<<NBA * TTK, 256>>>(scores, attn, ath, atl, mk);
    mma_gemm<2, 1><<<dim3(8, 8, NBA), 256, SMEMB>>>(
        ath, atl, vh, vl, nullptr, ch, cl, 1024, 1024,
        batch, batch, batch, nullptr, nullptr, 1.0f, cnt);
    // GEMM4 rows [0, 6144) — depends only on ctx batches [0,6)
    mma_gemm<1, 0><<<dim3(8, 8 * NBA, 1), 256, SMEMB>>>(
        ch, cl, woh, wol, out, nullptr, nullptr, 1024, 1024,
        0, 0, 0, b_out, x, scale, nullptr);

    // ---- Chain B (s2): batches [6,16) ----
    cudaStreamWaitEvent(s2, eG1, 0);    // h ready (side work already in-order)
    mma_gemm<0, 0><<<dim3(8, 8, NBB), 256, SMEMB, s2>>>(
        hh + offB, hl + offB, kh + offB, kl + offB, scores + offB, nullptr, nullptr,
        1024, 1024, batch, batch, batch, nullptr, nullptr, 1.0f, nullptr);
    softmax_kernel<<<NBB * TTK, 256, 0, s2>>>(
        scores + offB, attn + offB, ath + offB, atl + offB, mk + NBA * SEQ);
    mma_gemm<2, 1><<<dim3(8, 8, NBB), 256, SMEMB, s2>>>(
        ath + offB, atl + offB, vh + offB, vl + offB, nullptr, ch + offB, cl + offB,
        1024, 1024, batch, batch, batch, nullptr, nullptr, 1.0f, cnt + NBA);
    // GEMM4 rows [6144, 16384)
    mma_gemm<1, 0><<<dim3(8, 8 * NBB, 1), 256, SMEMB, s2>>>(
        ch + offB, cl + offB, woh, wol, out + offB, nullptr, nullptr,
        1024, 1024, 0, 0, 0, b_out, x + offB, scale, nullptr);
    cudaEventRecord(eB, s2);

    // Join chain B before returning.
    cudaStreamWaitEvent(0, eB, 0);
}